// round 15
// baseline (speedup 1.0000x reference)
#include <cuda_runtime.h>
#include <math.h>
#include <stdint.h>

typedef unsigned long long ull;

#define BB   8
#define FHH  8
#define NN   2048
#define TINN 5
#define HH1  32
#define HH2  64
#define KXX  40
#define TI   128          // gat rows per CTA
#define PS   130          // PsT row stride (floats, even)
#define SPLIT 4
#define ROWS_TOT (BB*NN)
#define NWORDS (NN/64)    // 32 ull mask words per row

// ---------------- scratch ----------------------------------------------------
__device__ float g_wx[BB*NN*4*HH2];
__device__ float g_hs[BB*NN*HH2];
__device__ float g_Wh[BB*NN*HH2];
__device__ float g_s [BB*NN];
__device__ float g_d [BB*NN];
__device__ unsigned int g_dmaxb[BB];
__device__ float g_pl  [SPLIT*ROWS_TOT];
__device__ float g_pacc[SPLIT*ROWS_TOT*HH2];
__device__ ull  g_amask[(size_t)ROWS_TOT*NWORDS];   // 4.2MB bitmask

// ---------------- f32x2 helpers ----------------------------------------------
__device__ __forceinline__ ull pack2(float lo, float hi) {
    ull r; asm("mov.b64 %0, {%1, %2};" : "=l"(r) : "f"(lo), "f"(hi)); return r;
}
__device__ __forceinline__ void unpack2(ull v, float& lo, float& hi) {
    asm("mov.b64 {%0, %1}, %2;" : "=f"(lo), "=f"(hi) : "l"(v));
}
__device__ __forceinline__ ull ffma2(ull a, ull b, ull c) {
    ull r; asm("fma.rn.f32x2 %0, %1, %2, %3;" : "=l"(r) : "l"(a), "l"(b), "l"(c)); return r;
}
__device__ __forceinline__ ull fadd2(ull a, ull b) {
    ull r; asm("add.rn.f32x2 %0, %1, %2;" : "=l"(r) : "l"(a), "l"(b)); return r;
}
__device__ __forceinline__ float fsig(float x) { return __fdividef(1.f, 1.f + __expf(-x)); }
__device__ __forceinline__ float ftanh(float x) {
    return fmaf(__fdividef(2.f, 1.f + __expf(-2.f*x)), 1.f, -1.f);
}
__device__ __forceinline__ unsigned int fkey(float f) {
    unsigned int b = __float_as_uint(f);
    return (b & 0x80000000u) ? ~b : (b | 0x80000000u);
}
__device__ __forceinline__ float fdec(unsigned int k) {
    return __uint_as_float((k & 0x80000000u) ? (k ^ 0x80000000u) : ~k);
}

// ============================================================================
// Kernel 1: fused h1/wx compute + adj bit-packing (overlapped DRAM stream).
// grid 2048 x 256. Warp w additionally packs adj row blockIdx*8 + w.
// ============================================================================
__global__ void k_hw(const float* __restrict__ hist,
                     const float* __restrict__ W1,
                     const float* __restrict__ b1,
                     const float* __restrict__ W_ih,
                     const float* __restrict__ b_ih,
                     const float* __restrict__ b_hh,
                     const int* __restrict__ adj) {
    __shared__ float xs[KXX*9];
    __shared__ float w1s[KXX*HH1];
    __shared__ float wih[HH1*256];
    __shared__ float bsI[256];
    __shared__ float h1s[HH1*9];
    int tid = threadIdx.x;
    int row0 = blockIdx.x * 8;
    int t  = row0 >> 11;
    int n0 = row0 & (NN-1);

    if (blockIdx.x == 0 && tid < BB) g_dmaxb[tid] = 0u;

    for (int i = tid; i < FHH*8*TINN; i += 256) {
        int f = i / 40, rem = i % 40;
        int n = rem / TINN, tt = rem % TINN;
        xs[(tt*FHH + f)*9 + n] = hist[((size_t)(t*FHH + f)*NN + n0 + n)*TINN + tt];
    }
    for (int i = tid; i < KXX*HH1; i += 256) {
        int k = i / KXX, idx = i % KXX;
        w1s[idx*HH1 + k] = W1[i];
    }
    for (int i = tid; i < HH1*256; i += 256) {
        int j = i >> 8, op = i & 255, u = op >> 2, gt = op & 3;
        wih[i] = W_ih[(gt*64 + u)*HH1 + j];
    }
    { int u = tid >> 2, gt = tid & 3; bsI[tid] = b_ih[gt*64+u] + b_hh[gt*64+u]; }
    __syncthreads();

    {
        int r = tid >> 5, j = tid & 31;
        float acc = b1[j];
        #pragma unroll 8
        for (int k = 0; k < KXX; k++)
            acc = fmaf(xs[k*9 + r], w1s[k*HH1 + j], acc);
        acc = acc > 0.f ? acc : expm1f(acc);
        h1s[j*9 + r] = acc;
    }
    __syncthreads();

    int u  = tid & 63;
    int r0 = (tid >> 6) * 2;
    ull acc[2][2];
    ull b0 = *(const ull*)&bsI[u*4], b1v = *(const ull*)&bsI[u*4+2];
    acc[0][0]=b0; acc[0][1]=b1v; acc[1][0]=b0; acc[1][1]=b1v;
    #pragma unroll 8
    for (int j = 0; j < HH1; j++) {
        ulonglong2 wv = *(const ulonglong2*)&wih[j*256 + u*4];
        float ha = h1s[j*9 + r0], hb = h1s[j*9 + r0 + 1];
        ull ha2 = pack2(ha, ha), hb2 = pack2(hb, hb);
        acc[0][0] = ffma2(wv.x, ha2, acc[0][0]);
        acc[0][1] = ffma2(wv.y, ha2, acc[0][1]);
        acc[1][0] = ffma2(wv.x, hb2, acc[1][0]);
        acc[1][1] = ffma2(wv.y, hb2, acc[1][1]);
    }
    #pragma unroll
    for (int nd = 0; nd < 2; nd++) {
        float v0,v1,v2,v3;
        unpack2(acc[nd][0], v0, v1);
        unpack2(acc[nd][1], v2, v3);
        *(float4*)&g_wx[(size_t)(row0 + r0 + nd)*256 + u*4] = make_float4(v0,v1,v2,v3);
    }

    // ---- adj bit-pack: warp w owns row gw = row0 + w --------------------------
    {
        int w = tid >> 5, lane = tid & 31;
        int gw = row0 + w;
        int b = gw >> 11, i = gw & (NN-1);
        const int* arow = adj + (size_t)(b*2 + 1)*NN*NN + (size_t)i*NN;
        unsigned* mrow = (unsigned*)&g_amask[(size_t)gw * NWORDS];
        #pragma unroll
        for (int half = 0; half < 2; half++) {
            unsigned mine = 0;
            #pragma unroll
            for (int jw = 0; jw < 32; jw++) {
                int v = arow[(half*32 + jw)*32 + lane] > 0;
                unsigned m = __ballot_sync(0xffffffffu, v);
                if (lane == jw) mine = m;
            }
            mrow[half*32 + lane] = mine;   // u32 word c = half*32+lane covers j in [32c,32c+32)
        }
    }
}

// ============================================================================
// Kernel 2: recurrent LSTM (W_hh part). 256 blocks x 256 thr, 8 nodes/block.
// ============================================================================
__global__ void __launch_bounds__(256) k_lstm2(const float* __restrict__ W_hh) {
    extern __shared__ float sm[];
    float* whh = sm;
    float* hsh = whh + 64*256;

    int tid = threadIdx.x;
    for (int i = tid; i < 64*256; i += 256) {
        int j = i >> 8, op = i & 255, u = op >> 2, gt = op & 3;
        whh[i] = W_hh[(gt*64 + u)*HH2 + j];
    }
    for (int i = tid; i < 64*9; i += 256) hsh[i] = 0.f;

    int u  = tid & 63;
    int nq = tid >> 6;
    int node0 = blockIdx.x * 8 + nq*2;

    float c[2] = {0.f,0.f};
    float4 wx4[2];
    #pragma unroll
    for (int n = 0; n < 2; n++)
        wx4[n] = *(const float4*)&g_wx[(size_t)(node0 + n)*256 + u*4];

    for (int t = 0; t < BB; t++) {
        __syncthreads();
        ull acc[2][2];
        #pragma unroll
        for (int n = 0; n < 2; n++) {
            acc[n][0] = pack2(wx4[n].x, wx4[n].y);
            acc[n][1] = pack2(wx4[n].z, wx4[n].w);
        }
        if (t < BB-1) {
            #pragma unroll
            for (int n = 0; n < 2; n++)
                wx4[n] = *(const float4*)&g_wx[(size_t)((t+1)*NN + node0 + n)*256 + u*4];
        }
        #pragma unroll 8
        for (int j = 0; j < HH2; j++) {
            ulonglong2 wv = *(const ulonglong2*)&whh[j*256 + u*4];
            #pragma unroll
            for (int n = 0; n < 2; n++) {
                float hv = hsh[j*9 + nq*2 + n];
                ull hv2 = pack2(hv, hv);
                acc[n][0] = ffma2(wv.x, hv2, acc[n][0]);
                acc[n][1] = ffma2(wv.y, hv2, acc[n][1]);
            }
        }
        __syncthreads();
        #pragma unroll
        for (int n = 0; n < 2; n++) {
            float gi,gf,gg,go;
            unpack2(acc[n][0], gi, gf);
            unpack2(acc[n][1], gg, go);
            c[n] = fsig(gf)*c[n] + fsig(gi)*ftanh(gg);
            float h = fsig(go)*ftanh(c[n]);
            hsh[u*9 + nq*2 + n] = h;
            g_hs[(size_t)(t*NN + node0 + n)*HH2 + u] = h;
        }
    }
}

// ============================================================================
// Kernel 3: Wh = hs @ Wg ; s,d; per-block dmax atomic. 512 blocks x 32 rows.
// ============================================================================
__global__ void k_wh(const float* __restrict__ Wg,
                     const float* __restrict__ a_src,
                     const float* __restrict__ a_dst) {
    __shared__ float wgs[64*64];
    __shared__ float hss[64*33];
    __shared__ float dred[32];
    int tid = threadIdx.x;
    int row0 = blockIdx.x * 32;
    for (int i = tid; i < 4096; i += 256) wgs[i] = Wg[i];
    for (int i = tid; i < 2048; i += 256) {
        int mm = i >> 6, u = i & 63;
        hss[u*33 + mm] = g_hs[(size_t)(row0 + mm)*HH2 + u];
    }
    __syncthreads();
    int cq = tid & 15;
    int c0 = cq * 4;
    float as0 = a_src[c0], as1 = a_src[c0+1], as2 = a_src[c0+2], as3 = a_src[c0+3];
    float ad0 = a_dst[c0], ad1 = a_dst[c0+1], ad2 = a_dst[c0+2], ad3 = a_dst[c0+3];
    #pragma unroll
    for (int rr = 0; rr < 2; rr++) {
        int m = rr*16 + (tid >> 4);
        ull acc0 = 0ull, acc1 = 0ull;
        #pragma unroll 8
        for (int u = 0; u < 64; u++) {
            float hv = hss[u*33 + m];
            ull hv2 = pack2(hv, hv);
            acc0 = ffma2(*(const ull*)&wgs[u*64 + c0],     hv2, acc0);
            acc1 = ffma2(*(const ull*)&wgs[u*64 + c0 + 2], hv2, acc1);
        }
        float wh0, wh1, wh2, wh3;
        unpack2(acc0, wh0, wh1);
        unpack2(acc1, wh2, wh3);
        *(float4*)&g_Wh[(size_t)(row0 + m)*HH2 + c0] = make_float4(wh0, wh1, wh2, wh3);
        float psum = wh0*as0 + wh1*as1 + wh2*as2 + wh3*as3;
        float dsum = wh0*ad0 + wh1*ad1 + wh2*ad2 + wh3*ad3;
        #pragma unroll
        for (int o = 8; o > 0; o >>= 1) {
            psum += __shfl_xor_sync(0xffffffffu, psum, o);
            dsum += __shfl_xor_sync(0xffffffffu, dsum, o);
        }
        if (cq == 0) {
            g_s[row0 + m] = psum;
            g_d[row0 + m] = dsum;
            dred[m] = dsum;
        }
    }
    __syncthreads();
    if (tid == 0) {
        float mx = dred[0];
        #pragma unroll
        for (int q = 1; q < 32; q++) mx = fmaxf(mx, dred[q]);
        atomicMax(&g_dmaxb[row0 >> 11], fkey(mx));
    }
}

// ============================================================================
// Kernel 4: GAT on bitmask. TI=128, 3 CTA/SM (65.5KB smem), thread tile
// 8 rows x 4 cols. Exp-free P, l folded into GEMM. grid (16, 8, SPLIT).
// ============================================================================
__global__ void __launch_bounds__(256, 3) k_gat() {
    extern __shared__ char smraw[];
    ull*   whs = (ull*)smraw;                      // [jj][c] dup pairs, 32KB
    float* PsT = (float*)(smraw + 32768);          // [jj][ii] stride PS, 33.3KB
    __shared__ float4 row_sh[TI];                  // (thr, Ap, An, -)

    int tid = threadIdx.x, lane = tid & 31, w = tid >> 5;
    int b = blockIdx.y, i0 = blockIdx.x * TI, sp = blockIdx.z;

    float dmax = fdec(g_dmaxb[b]);
    if (tid < TI) {
        float s = g_s[b*NN + i0 + tid];
        float sm = s + dmax;
        float M = sm > 0.f ? sm : 0.2f*sm;
        row_sh[tid] = make_float4(-s, __expf(sm - M), __expf(0.2f*sm - M), 0.f);
    }

    int rg  = tid >> 4;      // 16 row groups x 8 rows
    int cgp = tid & 15;      // cols cgp + 16k, k<4
    ull acc[4][4];           // [row pair][col]
    #pragma unroll
    for (int rp = 0; rp < 4; rp++)
        #pragma unroll
        for (int k = 0; k < 4; k++) acc[rp][k] = 0ull;
    ull lacc[4] = {0ull, 0ull, 0ull, 0ull};

    const int JT = (NN/64)/SPLIT;
    const ull* mbase = g_amask + (size_t)(b*NN + i0) * NWORDS;

    for (int jtl = 0; jtl < JT; jtl++) {
        int jtg = sp * JT + jtl;
        int j0  = jtg * 64;
        __syncthreads();

        for (int i = tid; i < 2048; i += 256) {
            float2 v = *(const float2*)&g_Wh[(size_t)(b*NN + j0)*64 + 2*i];
            whs[2*i]   = pack2(v.x, v.x);
            whs[2*i+1] = pack2(v.y, v.y);
        }

        float d0 = g_d[b*NN + j0 + lane];
        float d1 = g_d[b*NN + j0 + lane + 32];
        float bp0 = __expf(d0 - dmax);
        float bp1 = __expf(d1 - dmax);
        float bm0 = __expf(0.2f*(d0 - dmax));
        float bm1 = __expf(0.2f*(d1 - dmax));

        // P-phase: warp w -> rows w*16..w*16+15, masks via broadcast LDG.64
        #pragma unroll
        for (int batch = 0; batch < 2; batch++) {
            ull aw[8];
            #pragma unroll
            for (int q = 0; q < 8; q++)
                aw[q] = mbase[(size_t)(w*16 + batch*8 + q)*NWORDS + jtg];
            #pragma unroll
            for (int q = 0; q < 8; q++) {
                int ii = w*16 + batch*8 + q;
                float4 rs = row_sh[ii];
                float c0 = (d0 > rs.x) ? rs.y*bp0 : rs.z*bm0;
                float c1 = (d1 > rs.x) ? rs.y*bp1 : rs.z*bm1;
                c0 = ((unsigned)(aw[q] >> lane) & 1u)        ? c0 : 0.f;
                c1 = ((unsigned)(aw[q] >> (lane + 32)) & 1u) ? c1 : 0.f;
                PsT[lane*PS + ii]      = c0;
                PsT[(lane+32)*PS + ii] = c1;
            }
        }
        __syncthreads();

        const float* pbase = PsT + rg*8;
        const ull*   wbase = whs + cgp;
        #pragma unroll 2
        for (int jj = 0; jj < 64; jj++) {
            ull pp[4];
            #pragma unroll
            for (int rp = 0; rp < 4; rp++)
                pp[rp] = *(const ull*)&pbase[jj*PS + 2*rp];
            #pragma unroll
            for (int rp = 0; rp < 4; rp++)
                lacc[rp] = fadd2(lacc[rp], pp[rp]);
            #pragma unroll
            for (int k = 0; k < 4; k++) {
                ull wd = wbase[jj*64 + 16*k];
                #pragma unroll
                for (int rp = 0; rp < 4; rp++)
                    acc[rp][k] = ffma2(wd, pp[rp], acc[rp][k]);
            }
        }
    }

    if (cgp == 0) {
        size_t lb = (size_t)sp*ROWS_TOT + b*NN + i0 + rg*8;
        #pragma unroll
        for (int rp = 0; rp < 4; rp++) {
            float l0, l1;
            unpack2(lacc[rp], l0, l1);
            g_pl[lb + 2*rp]     = l0;
            g_pl[lb + 2*rp + 1] = l1;
        }
    }
    #pragma unroll
    for (int rp = 0; rp < 4; rp++) {
        size_t base0 = ((size_t)sp*ROWS_TOT + b*NN + i0 + rg*8 + 2*rp)     * HH2;
        size_t base1 = ((size_t)sp*ROWS_TOT + b*NN + i0 + rg*8 + 2*rp + 1) * HH2;
        #pragma unroll
        for (int k = 0; k < 4; k++) {
            float va, vb;
            unpack2(acc[rp][k], va, vb);
            g_pacc[base0 + cgp + 16*k] = va;
            g_pacc[base1 + cgp + 16*k] = vb;
        }
    }
}

// ============================================================================
// Kernel 5: combine additive split-K partials; normalize + elu.
// ============================================================================
__global__ void k_comb(float* __restrict__ out) {
    int tid = threadIdx.x;
    int r = blockIdx.x * 4 + (tid >> 6);
    int c = tid & 63;
    float l = 0.f, val = 0.f;
    #pragma unroll
    for (int s = 0; s < SPLIT; s++) {
        l   += g_pl[s*ROWS_TOT + r];
        val += g_pacc[((size_t)s*ROWS_TOT + r)*HH2 + c];
    }
    if (!(l > 0.f)) l = 1.f;
    float z = val / l;
    out[(size_t)r*HH2 + c] = z > 0.f ? z : expm1f(z);
}

// ============================================================================
extern "C" void kernel_launch(void* const* d_in, const int* in_sizes, int n_in,
                              void* d_out, int out_size) {
    const float* hist  = (const float*)d_in[0];
    const int*   adj   = (const int*)  d_in[1];
    const float* W1    = (const float*)d_in[2];
    const float* b1    = (const float*)d_in[3];
    const float* W_ih  = (const float*)d_in[4];
    const float* W_hh  = (const float*)d_in[5];
    const float* b_ih  = (const float*)d_in[6];
    const float* b_hh  = (const float*)d_in[7];
    const float* Wg    = (const float*)d_in[8];
    const float* a_src = (const float*)d_in[9];
    const float* a_dst = (const float*)d_in[10];
    float* out = (float*)d_out;

    const size_t sm_lstm = (size_t)(64*256 + 64*9) * sizeof(float);
    const size_t sm_gat  = (size_t)32768 + (size_t)(64*PS*4);
    cudaFuncSetAttribute(k_lstm2, cudaFuncAttributeMaxDynamicSharedMemorySize, (int)sm_lstm);
    cudaFuncSetAttribute(k_gat,   cudaFuncAttributeMaxDynamicSharedMemorySize, (int)sm_gat);

    k_hw   <<<2048, 256>>>(hist, W1, b1, W_ih, b_ih, b_hh, adj);
    k_lstm2<<<256,  256, sm_lstm>>>(W_hh);
    k_wh   <<<512,  256>>>(Wg, a_src, a_dst);
    dim3 g4(NN/TI, BB, SPLIT);
    k_gat  <<<g4, 256, sm_gat>>>();
    k_comb <<<4096, 256>>>(out);
}

// round 16
// speedup vs baseline: 1.1310x; 1.1310x over previous
#include <cuda_runtime.h>
#include <math.h>
#include <stdint.h>

typedef unsigned long long ull;

#define BB   8
#define FHH  8
#define NN   2048
#define TINN 5
#define HH1  32
#define HH2  64
#define KXX  40
#define TI   256          // gat rows per CTA
#define PS   258          // PsT row stride (floats, even)
#define SPLIT 4
#define ROWS_TOT (BB*NN)
#define NWORDS (NN/64)    // 32 ull mask words per row

// ---------------- scratch ----------------------------------------------------
__device__ float g_wx[BB*NN*4*HH2];
__device__ float g_Wh[BB*NN*HH2];
__device__ float g_s [BB*NN];
__device__ float g_d [BB*NN];
__device__ unsigned int g_dmaxb[BB];
__device__ float g_pl  [SPLIT*ROWS_TOT];
__device__ float g_pacc[SPLIT*ROWS_TOT*HH2];
__device__ ull  g_amask[(size_t)ROWS_TOT*NWORDS];   // 4.2MB bitmask

// ---------------- f32x2 helpers ----------------------------------------------
__device__ __forceinline__ ull pack2(float lo, float hi) {
    ull r; asm("mov.b64 %0, {%1, %2};" : "=l"(r) : "f"(lo), "f"(hi)); return r;
}
__device__ __forceinline__ void unpack2(ull v, float& lo, float& hi) {
    asm("mov.b64 {%0, %1}, %2;" : "=f"(lo), "=f"(hi) : "l"(v));
}
__device__ __forceinline__ ull ffma2(ull a, ull b, ull c) {
    ull r; asm("fma.rn.f32x2 %0, %1, %2, %3;" : "=l"(r) : "l"(a), "l"(b), "l"(c)); return r;
}
__device__ __forceinline__ ull fadd2(ull a, ull b) {
    ull r; asm("add.rn.f32x2 %0, %1, %2;" : "=l"(r) : "l"(a), "l"(b)); return r;
}
__device__ __forceinline__ ull fmul2(ull a, ull b) {
    ull r; asm("mul.rn.f32x2 %0, %1, %2;" : "=l"(r) : "l"(a), "l"(b)); return r;
}
__device__ __forceinline__ float fsig(float x) { return __fdividef(1.f, 1.f + __expf(-x)); }
__device__ __forceinline__ float ftanh(float x) {
    return fmaf(__fdividef(2.f, 1.f + __expf(-2.f*x)), 1.f, -1.f);
}
__device__ __forceinline__ unsigned int fkey(float f) {
    unsigned int b = __float_as_uint(f);
    return (b & 0x80000000u) ? ~b : (b | 0x80000000u);
}
__device__ __forceinline__ float fdec(unsigned int k) {
    return __uint_as_float((k & 0x80000000u) ? (k ^ 0x80000000u) : ~k);
}

// ============================================================================
// Kernel 1: fused h1/wx compute + adj bit-packing (overlapped DRAM stream).
// ============================================================================
__global__ void k_hw(const float* __restrict__ hist,
                     const float* __restrict__ W1,
                     const float* __restrict__ b1,
                     const float* __restrict__ W_ih,
                     const float* __restrict__ b_ih,
                     const float* __restrict__ b_hh,
                     const int* __restrict__ adj) {
    __shared__ float xs[KXX*9];
    __shared__ float w1s[KXX*HH1];
    __shared__ float wih[HH1*256];
    __shared__ float bsI[256];
    __shared__ float h1s[HH1*9];
    int tid = threadIdx.x;
    int row0 = blockIdx.x * 8;
    int t  = row0 >> 11;
    int n0 = row0 & (NN-1);

    if (blockIdx.x == 0 && tid < BB) g_dmaxb[tid] = 0u;

    for (int i = tid; i < FHH*8*TINN; i += 256) {
        int f = i / 40, rem = i % 40;
        int n = rem / TINN, tt = rem % TINN;
        xs[(tt*FHH + f)*9 + n] = hist[((size_t)(t*FHH + f)*NN + n0 + n)*TINN + tt];
    }
    for (int i = tid; i < KXX*HH1; i += 256) {
        int k = i / KXX, idx = i % KXX;
        w1s[idx*HH1 + k] = W1[i];
    }
    for (int i = tid; i < HH1*256; i += 256) {
        int j = i >> 8, op = i & 255, u = op >> 2, gt = op & 3;
        wih[i] = W_ih[(gt*64 + u)*HH1 + j];
    }
    { int u = tid >> 2, gt = tid & 3; bsI[tid] = b_ih[gt*64+u] + b_hh[gt*64+u]; }
    __syncthreads();

    {
        int r = tid >> 5, j = tid & 31;
        float acc = b1[j];
        #pragma unroll 8
        for (int k = 0; k < KXX; k++)
            acc = fmaf(xs[k*9 + r], w1s[k*HH1 + j], acc);
        acc = acc > 0.f ? acc : expm1f(acc);
        h1s[j*9 + r] = acc;
    }
    __syncthreads();

    int u  = tid & 63;
    int r0 = (tid >> 6) * 2;
    ull acc[2][2];
    ull b0 = *(const ull*)&bsI[u*4], b1v = *(const ull*)&bsI[u*4+2];
    acc[0][0]=b0; acc[0][1]=b1v; acc[1][0]=b0; acc[1][1]=b1v;
    #pragma unroll 8
    for (int j = 0; j < HH1; j++) {
        ulonglong2 wv = *(const ulonglong2*)&wih[j*256 + u*4];
        float ha = h1s[j*9 + r0], hb = h1s[j*9 + r0 + 1];
        ull ha2 = pack2(ha, ha), hb2 = pack2(hb, hb);
        acc[0][0] = ffma2(wv.x, ha2, acc[0][0]);
        acc[0][1] = ffma2(wv.y, ha2, acc[0][1]);
        acc[1][0] = ffma2(wv.x, hb2, acc[1][0]);
        acc[1][1] = ffma2(wv.y, hb2, acc[1][1]);
    }
    #pragma unroll
    for (int nd = 0; nd < 2; nd++) {
        float v0,v1,v2,v3;
        unpack2(acc[nd][0], v0, v1);
        unpack2(acc[nd][1], v2, v3);
        *(float4*)&g_wx[(size_t)(row0 + r0 + nd)*256 + u*4] = make_float4(v0,v1,v2,v3);
    }

    // ---- adj bit-pack: warp w owns row gw = row0 + w ----
    {
        int w = tid >> 5, lane = tid & 31;
        int gw = row0 + w;
        int b = gw >> 11, i = gw & (NN-1);
        const int* arow = adj + (size_t)(b*2 + 1)*NN*NN + (size_t)i*NN;
        unsigned* mrow = (unsigned*)&g_amask[(size_t)gw * NWORDS];
        #pragma unroll
        for (int half = 0; half < 2; half++) {
            unsigned mine = 0;
            #pragma unroll
            for (int jw = 0; jw < 32; jw++) {
                int v = arow[(half*32 + jw)*32 + lane] > 0;
                unsigned m = __ballot_sync(0xffffffffu, v);
                if (lane == jw) mine = m;
            }
            mrow[half*32 + lane] = mine;
        }
    }
}

// ============================================================================
// Kernel 2: fused LSTM + Wh + s/d + dmax. 256 blocks x 256 thr, 8 nodes/block.
// Per step: gates (as before) -> h into hsh -> Wh = h@Wg (dup-pair smem Wg),
// s/d via fmul2 + warp shuffle reduce, dmax via smem atomicMax.
// k_wh and g_hs are eliminated.
// ============================================================================
__global__ void __launch_bounds__(256) k_lstm3(const float* __restrict__ W_hh,
                                               const float* __restrict__ Wg,
                                               const float* __restrict__ a_src,
                                               const float* __restrict__ a_dst) {
    extern __shared__ float sm[];
    float* whh = sm;                        // [64][256] 64KB
    ull*   wgd = (ull*)(sm + 64*256);       // [u][c] dup pairs 32KB
    float* hsh = (float*)(wgd + 64*64);     // [u][node] stride 10, 2.5KB
    __shared__ ull red_s[8], red_d[8];
    __shared__ unsigned dml[8];

    int tid = threadIdx.x;
    int lane = tid & 31, w = tid >> 5;
    for (int i = tid; i < 64*256; i += 256) {
        int j = i >> 8, op = i & 255, u = op >> 2, gt = op & 3;
        whh[i] = W_hh[(gt*64 + u)*HH2 + j];
    }
    for (int i = tid; i < 4096; i += 256) {
        float v = Wg[i];
        wgd[i] = pack2(v, v);
    }
    for (int i = tid; i < 64*10; i += 256) hsh[i] = 0.f;
    if (tid < 8) dml[tid] = 0u;

    int u  = tid & 63;          // unit (gate loop) / column c (Wh phase)
    int nq = tid >> 6;          // node group (2 nodes)
    int node0 = blockIdx.x * 8 + nq*2;

    float asv = a_src[u], adv = a_dst[u];
    ull as2 = pack2(asv, asv), ad2 = pack2(adv, adv);

    float c[2] = {0.f,0.f};
    float4 wx4[2];
    #pragma unroll
    for (int n = 0; n < 2; n++)
        wx4[n] = *(const float4*)&g_wx[(size_t)(node0 + n)*256 + u*4];

    for (int t = 0; t < BB; t++) {
        __syncthreads();                       // A: hsh/red stable
        ull acc[2][2];
        #pragma unroll
        for (int n = 0; n < 2; n++) {
            acc[n][0] = pack2(wx4[n].x, wx4[n].y);
            acc[n][1] = pack2(wx4[n].z, wx4[n].w);
        }
        if (t < BB-1) {
            #pragma unroll
            for (int n = 0; n < 2; n++)
                wx4[n] = *(const float4*)&g_wx[(size_t)((t+1)*NN + node0 + n)*256 + u*4];
        }
        #pragma unroll 8
        for (int j = 0; j < HH2; j++) {
            ulonglong2 wv = *(const ulonglong2*)&whh[j*256 + u*4];
            #pragma unroll
            for (int n = 0; n < 2; n++) {
                float hv = hsh[j*10 + nq*2 + n];
                ull hv2 = pack2(hv, hv);
                acc[n][0] = ffma2(wv.x, hv2, acc[n][0]);
                acc[n][1] = ffma2(wv.y, hv2, acc[n][1]);
            }
        }
        __syncthreads();                       // B: gate reads of old hsh done
        #pragma unroll
        for (int n = 0; n < 2; n++) {
            float gi,gf,gg,go;
            unpack2(acc[n][0], gi, gf);
            unpack2(acc[n][1], gg, go);
            c[n] = fsig(gf)*c[n] + fsig(gi)*ftanh(gg);
            float h = fsig(go)*ftanh(c[n]);
            hsh[u*10 + nq*2 + n] = h;
        }
        __syncthreads();                       // C: new hsh complete

        // ---- Wh phase: thread = (col u, node pair nq) ----
        ull whacc = 0ull;
        #pragma unroll 8
        for (int j = 0; j < HH2; j++) {
            ull h2 = *(const ull*)&hsh[j*10 + nq*2];
            whacc = ffma2(wgd[j*64 + u], h2, whacc);
        }
        float wh0, wh1;
        unpack2(whacc, wh0, wh1);
        g_Wh[(size_t)(t*NN + node0)*HH2 + u]     = wh0;
        g_Wh[(size_t)(t*NN + node0 + 1)*HH2 + u] = wh1;

        ull sp = fmul2(whacc, as2);
        ull dp = fmul2(whacc, ad2);
        #pragma unroll
        for (int o = 16; o > 0; o >>= 1) {
            sp = fadd2(sp, __shfl_xor_sync(0xffffffffu, sp, o));
            dp = fadd2(dp, __shfl_xor_sync(0xffffffffu, dp, o));
        }
        if (lane == 0) { red_s[w] = sp; red_d[w] = dp; }
        __syncthreads();                       // D: red ready
        if (tid < 4) {
            ull st = fadd2(red_s[tid*2], red_s[tid*2 + 1]);
            ull dt = fadd2(red_d[tid*2], red_d[tid*2 + 1]);
            float s0, s1, d0, d1;
            unpack2(st, s0, s1);
            unpack2(dt, d0, d1);
            int nb = blockIdx.x*8 + tid*2;
            g_s[t*NN + nb]     = s0;
            g_s[t*NN + nb + 1] = s1;
            g_d[t*NN + nb]     = d0;
            g_d[t*NN + nb + 1] = d1;
            atomicMax(&dml[t], fkey(fmaxf(d0, d1)));
        }
    }
    __syncthreads();
    if (tid < 8) atomicMax(&g_dmaxb[tid], dml[tid]);
}

// ============================================================================
// Kernel 3: GAT on bitmask. TI=256, SPLIT=4, thread tile 8x8 (R14 config).
// Exp-free P (rank-1, fixed shift), l folded into GEMM. grid (8, 8, 4).
// ============================================================================
__global__ void __launch_bounds__(256, 2) k_gat() {
    extern __shared__ char smraw[];
    ull*   whs = (ull*)smraw;                      // [jj][c] dup pairs, 32KB
    float* PsT = (float*)(smraw + 32768);          // [jj][ii] stride PS, 66KB
    __shared__ float4 row_sh[TI];                  // (thr, Ap, An, -)

    int tid = threadIdx.x, lane = tid & 31, w = tid >> 5;
    int b = blockIdx.y, i0 = blockIdx.x * TI, sp = blockIdx.z;

    float dmax = fdec(g_dmaxb[b]);
    {
        float s = g_s[b*NN + i0 + tid];
        float sm = s + dmax;
        float M = sm > 0.f ? sm : 0.2f*sm;
        row_sh[tid] = make_float4(-s, __expf(sm - M), __expf(0.2f*sm - M), 0.f);
    }

    int rg  = tid >> 3;      // 32 row groups x 8 rows
    int cgp = tid & 7;       // cols cgp + 8k
    ull acc[4][8];
    #pragma unroll
    for (int rp = 0; rp < 4; rp++)
        #pragma unroll
        for (int k = 0; k < 8; k++) acc[rp][k] = 0ull;
    ull lacc[4] = {0ull, 0ull, 0ull, 0ull};

    const int JT = (NN/64)/SPLIT;
    const ull* mbase = g_amask + (size_t)(b*NN + i0) * NWORDS;

    for (int jtl = 0; jtl < JT; jtl++) {
        int jtg = sp * JT + jtl;
        int j0  = jtg * 64;
        __syncthreads();

        for (int i = tid; i < 2048; i += 256) {
            float2 v = *(const float2*)&g_Wh[(size_t)(b*NN + j0)*64 + 2*i];
            whs[2*i]   = pack2(v.x, v.x);
            whs[2*i+1] = pack2(v.y, v.y);
        }

        float d0 = g_d[b*NN + j0 + lane];
        float d1 = g_d[b*NN + j0 + lane + 32];
        float bp0 = __expf(d0 - dmax);
        float bp1 = __expf(d1 - dmax);
        float bm0 = __expf(0.2f*(d0 - dmax));
        float bm1 = __expf(0.2f*(d1 - dmax));

        #pragma unroll
        for (int batch = 0; batch < 4; batch++) {
            ull aw[8];
            #pragma unroll
            for (int q = 0; q < 8; q++)
                aw[q] = mbase[(size_t)(w*32 + batch*8 + q)*NWORDS + jtg];
            #pragma unroll
            for (int q = 0; q < 8; q++) {
                int ii = w*32 + batch*8 + q;
                float4 rs = row_sh[ii];
                float c0 = (d0 > rs.x) ? rs.y*bp0 : rs.z*bm0;
                float c1 = (d1 > rs.x) ? rs.y*bp1 : rs.z*bm1;
                c0 = ((unsigned)(aw[q] >> lane) & 1u)        ? c0 : 0.f;
                c1 = ((unsigned)(aw[q] >> (lane + 32)) & 1u) ? c1 : 0.f;
                PsT[lane*PS + ii]      = c0;
                PsT[(lane+32)*PS + ii] = c1;
            }
        }
        __syncthreads();

        const float* pbase = PsT + rg*8;
        const ull*   wbase = whs + cgp;
        #pragma unroll 2
        for (int jj = 0; jj < 64; jj++) {
            ull pp[4];
            #pragma unroll
            for (int rp = 0; rp < 4; rp++)
                pp[rp] = *(const ull*)&pbase[jj*PS + 2*rp];
            #pragma unroll
            for (int rp = 0; rp < 4; rp++)
                lacc[rp] = fadd2(lacc[rp], pp[rp]);
            #pragma unroll
            for (int k = 0; k < 8; k++) {
                ull wd = wbase[jj*64 + 8*k];
                #pragma unroll
                for (int rp = 0; rp < 4; rp++)
                    acc[rp][k] = ffma2(wd, pp[rp], acc[rp][k]);
            }
        }
    }

    if (cgp == 0) {
        size_t lb = (size_t)sp*ROWS_TOT + b*NN + i0 + rg*8;
        #pragma unroll
        for (int rp = 0; rp < 4; rp++) {
            float l0, l1;
            unpack2(lacc[rp], l0, l1);
            g_pl[lb + 2*rp]     = l0;
            g_pl[lb + 2*rp + 1] = l1;
        }
    }
    #pragma unroll
    for (int rp = 0; rp < 4; rp++) {
        size_t base0 = ((size_t)sp*ROWS_TOT + b*NN + i0 + rg*8 + 2*rp)     * HH2;
        size_t base1 = ((size_t)sp*ROWS_TOT + b*NN + i0 + rg*8 + 2*rp + 1) * HH2;
        #pragma unroll
        for (int k = 0; k < 8; k++) {
            float va, vb;
            unpack2(acc[rp][k], va, vb);
            g_pacc[base0 + cgp + 8*k] = va;
            g_pacc[base1 + cgp + 8*k] = vb;
        }
    }
}

// ============================================================================
// Kernel 4: combine additive split-K partials; normalize + elu.
// ============================================================================
__global__ void k_comb(float* __restrict__ out) {
    int tid = threadIdx.x;
    int r = blockIdx.x * 4 + (tid >> 6);
    int c = tid & 63;
    float l = 0.f, val = 0.f;
    #pragma unroll
    for (int s = 0; s < SPLIT; s++) {
        l   += g_pl[s*ROWS_TOT + r];
        val += g_pacc[((size_t)s*ROWS_TOT + r)*HH2 + c];
    }
    if (!(l > 0.f)) l = 1.f;
    float z = val / l;
    out[(size_t)r*HH2 + c] = z > 0.f ? z : expm1f(z);
}

// ============================================================================
extern "C" void kernel_launch(void* const* d_in, const int* in_sizes, int n_in,
                              void* d_out, int out_size) {
    const float* hist  = (const float*)d_in[0];
    const int*   adj   = (const int*)  d_in[1];
    const float* W1    = (const float*)d_in[2];
    const float* b1    = (const float*)d_in[3];
    const float* W_ih  = (const float*)d_in[4];
    const float* W_hh  = (const float*)d_in[5];
    const float* b_ih  = (const float*)d_in[6];
    const float* b_hh  = (const float*)d_in[7];
    const float* Wg    = (const float*)d_in[8];
    const float* a_src = (const float*)d_in[9];
    const float* a_dst = (const float*)d_in[10];
    float* out = (float*)d_out;

    const size_t sm_lstm = (size_t)(64*256)*4 + (size_t)(64*64)*8 + (size_t)(64*10)*4;
    const size_t sm_gat  = (size_t)32768 + (size_t)(64*PS*4);
    cudaFuncSetAttribute(k_lstm3, cudaFuncAttributeMaxDynamicSharedMemorySize, (int)sm_lstm);
    cudaFuncSetAttribute(k_gat,   cudaFuncAttributeMaxDynamicSharedMemorySize, (int)sm_gat);

    k_hw   <<<2048, 256>>>(hist, W1, b1, W_ih, b_ih, b_hh, adj);
    k_lstm3<<<256,  256, sm_lstm>>>(W_hh, Wg, a_src, a_dst);
    dim3 g4(NN/TI, BB, SPLIT);
    k_gat  <<<g4, 256, sm_gat>>>();
    k_comb <<<4096, 256>>>(out);
}

// round 17
// speedup vs baseline: 1.1412x; 1.0090x over previous
#include <cuda_runtime.h>
#include <math.h>
#include <stdint.h>

typedef unsigned long long ull;

#define BB   8
#define FHH  8
#define NN   2048
#define TINN 5
#define HH1  32
#define HH2  64
#define KXX  40
#define TI   256          // gat rows per CTA
#define PS   258          // PsT row stride (floats, even)
#define SPLIT 4
#define ROWS_TOT (BB*NN)
#define NWORDS (NN/64)    // 32 ull mask words per row

// ---------------- scratch ----------------------------------------------------
__device__ float g_wx[BB*NN*4*HH2];
__device__ float g_Wh[BB*NN*HH2];
__device__ float g_s [BB*NN];
__device__ float g_d [BB*NN];
__device__ unsigned int g_dmaxb[BB];
__device__ float g_pl  [SPLIT*ROWS_TOT];
__device__ float g_pacc[SPLIT*ROWS_TOT*HH2];
__device__ ull  g_amask[(size_t)ROWS_TOT*NWORDS];   // 4.2MB bitmask

// ---------------- f32x2 helpers ----------------------------------------------
__device__ __forceinline__ ull pack2(float lo, float hi) {
    ull r; asm("mov.b64 %0, {%1, %2};" : "=l"(r) : "f"(lo), "f"(hi)); return r;
}
__device__ __forceinline__ void unpack2(ull v, float& lo, float& hi) {
    asm("mov.b64 {%0, %1}, %2;" : "=f"(lo), "=f"(hi) : "l"(v));
}
__device__ __forceinline__ ull ffma2(ull a, ull b, ull c) {
    ull r; asm("fma.rn.f32x2 %0, %1, %2, %3;" : "=l"(r) : "l"(a), "l"(b), "l"(c)); return r;
}
__device__ __forceinline__ ull fadd2(ull a, ull b) {
    ull r; asm("add.rn.f32x2 %0, %1, %2;" : "=l"(r) : "l"(a), "l"(b)); return r;
}
__device__ __forceinline__ ull fmul2(ull a, ull b) {
    ull r; asm("mul.rn.f32x2 %0, %1, %2;" : "=l"(r) : "l"(a), "l"(b)); return r;
}
__device__ __forceinline__ float fsig(float x) { return __fdividef(1.f, 1.f + __expf(-x)); }
__device__ __forceinline__ float ftanh(float x) {
    return fmaf(__fdividef(2.f, 1.f + __expf(-2.f*x)), 1.f, -1.f);
}
__device__ __forceinline__ unsigned int fkey(float f) {
    unsigned int b = __float_as_uint(f);
    return (b & 0x80000000u) ? ~b : (b | 0x80000000u);
}
__device__ __forceinline__ float fdec(unsigned int k) {
    return __uint_as_float((k & 0x80000000u) ? (k ^ 0x80000000u) : ~k);
}

// ============================================================================
// Kernel 1: fused h1/wx compute + adj bit-packing (MLP-8 batched loads).
// ============================================================================
__global__ void k_hw(const float* __restrict__ hist,
                     const float* __restrict__ W1,
                     const float* __restrict__ b1,
                     const float* __restrict__ W_ih,
                     const float* __restrict__ b_ih,
                     const float* __restrict__ b_hh,
                     const int* __restrict__ adj) {
    __shared__ float xs[KXX*9];
    __shared__ float w1s[KXX*HH1];
    __shared__ float wih[HH1*256];
    __shared__ float bsI[256];
    __shared__ float h1s[HH1*9];
    int tid = threadIdx.x;
    int row0 = blockIdx.x * 8;
    int t  = row0 >> 11;
    int n0 = row0 & (NN-1);

    if (blockIdx.x == 0 && tid < BB) g_dmaxb[tid] = 0u;

    for (int i = tid; i < FHH*8*TINN; i += 256) {
        int f = i / 40, rem = i % 40;
        int n = rem / TINN, tt = rem % TINN;
        xs[(tt*FHH + f)*9 + n] = hist[((size_t)(t*FHH + f)*NN + n0 + n)*TINN + tt];
    }
    for (int i = tid; i < KXX*HH1; i += 256) {
        int k = i / KXX, idx = i % KXX;
        w1s[idx*HH1 + k] = W1[i];
    }
    for (int i = tid; i < HH1*256; i += 256) {
        int j = i >> 8, op = i & 255, u = op >> 2, gt = op & 3;
        wih[i] = W_ih[(gt*64 + u)*HH1 + j];
    }
    { int u = tid >> 2, gt = tid & 3; bsI[tid] = b_ih[gt*64+u] + b_hh[gt*64+u]; }
    __syncthreads();

    {
        int r = tid >> 5, j = tid & 31;
        float acc = b1[j];
        #pragma unroll 8
        for (int k = 0; k < KXX; k++)
            acc = fmaf(xs[k*9 + r], w1s[k*HH1 + j], acc);
        acc = acc > 0.f ? acc : expm1f(acc);
        h1s[j*9 + r] = acc;
    }
    __syncthreads();

    int u  = tid & 63;
    int r0 = (tid >> 6) * 2;
    ull acc[2][2];
    ull b0 = *(const ull*)&bsI[u*4], b1v = *(const ull*)&bsI[u*4+2];
    acc[0][0]=b0; acc[0][1]=b1v; acc[1][0]=b0; acc[1][1]=b1v;
    #pragma unroll 8
    for (int j = 0; j < HH1; j++) {
        ulonglong2 wv = *(const ulonglong2*)&wih[j*256 + u*4];
        float ha = h1s[j*9 + r0], hb = h1s[j*9 + r0 + 1];
        ull ha2 = pack2(ha, ha), hb2 = pack2(hb, hb);
        acc[0][0] = ffma2(wv.x, ha2, acc[0][0]);
        acc[0][1] = ffma2(wv.y, ha2, acc[0][1]);
        acc[1][0] = ffma2(wv.x, hb2, acc[1][0]);
        acc[1][1] = ffma2(wv.y, hb2, acc[1][1]);
    }
    #pragma unroll
    for (int nd = 0; nd < 2; nd++) {
        float v0,v1,v2,v3;
        unpack2(acc[nd][0], v0, v1);
        unpack2(acc[nd][1], v2, v3);
        *(float4*)&g_wx[(size_t)(row0 + r0 + nd)*256 + u*4] = make_float4(v0,v1,v2,v3);
    }

    // ---- adj bit-pack: warp w owns row gw = row0 + w. MLP-8 batched. ----
    {
        int w = tid >> 5, lane = tid & 31;
        int gw = row0 + w;
        int b = gw >> 11, i = gw & (NN-1);
        const int* arow = adj + (size_t)(b*2 + 1)*NN*NN + (size_t)i*NN;
        unsigned* mrow = (unsigned*)&g_amask[(size_t)gw * NWORDS];
        unsigned mine0 = 0, mine1 = 0;     // words c=lane, c=lane+32
        #pragma unroll
        for (int c0 = 0; c0 < 64; c0 += 8) {
            int v[8];
            #pragma unroll
            for (int q = 0; q < 8; q++)
                v[q] = arow[(c0 + q)*32 + lane];
            #pragma unroll
            for (int q = 0; q < 8; q++) {
                int c = c0 + q;
                unsigned m = __ballot_sync(0xffffffffu, v[q] > 0);
                if (lane == (c & 31)) {
                    if (c < 32) mine0 = m; else mine1 = m;
                }
            }
        }
        mrow[lane]      = mine0;   // u32 word c covers j in [32c, 32c+32)
        mrow[lane + 32] = mine1;
    }
}

// ============================================================================
// Kernel 2: fused LSTM + Wh + s/d + dmax. 256 blocks x 256 thr, 8 nodes/block.
// ============================================================================
__global__ void __launch_bounds__(256) k_lstm3(const float* __restrict__ W_hh,
                                               const float* __restrict__ Wg,
                                               const float* __restrict__ a_src,
                                               const float* __restrict__ a_dst) {
    extern __shared__ float sm[];
    float* whh = sm;                        // [64][256] 64KB
    ull*   wgd = (ull*)(sm + 64*256);       // [u][c] dup pairs 32KB
    float* hsh = (float*)(wgd + 64*64);     // [u][node] stride 10
    __shared__ ull red_s[8], red_d[8];
    __shared__ unsigned dml[8];

    int tid = threadIdx.x;
    int lane = tid & 31, w = tid >> 5;
    for (int i = tid; i < 64*256; i += 256) {
        int j = i >> 8, op = i & 255, u = op >> 2, gt = op & 3;
        whh[i] = W_hh[(gt*64 + u)*HH2 + j];
    }
    for (int i = tid; i < 4096; i += 256) {
        float v = Wg[i];
        wgd[i] = pack2(v, v);
    }
    for (int i = tid; i < 64*10; i += 256) hsh[i] = 0.f;
    if (tid < 8) dml[tid] = 0u;

    int u  = tid & 63;
    int nq = tid >> 6;
    int node0 = blockIdx.x * 8 + nq*2;

    float asv = a_src[u], adv = a_dst[u];
    ull as2 = pack2(asv, asv), ad2 = pack2(adv, adv);

    float c[2] = {0.f,0.f};
    float4 wx4[2];
    #pragma unroll
    for (int n = 0; n < 2; n++)
        wx4[n] = *(const float4*)&g_wx[(size_t)(node0 + n)*256 + u*4];

    for (int t = 0; t < BB; t++) {
        __syncthreads();
        ull acc[2][2];
        #pragma unroll
        for (int n = 0; n < 2; n++) {
            acc[n][0] = pack2(wx4[n].x, wx4[n].y);
            acc[n][1] = pack2(wx4[n].z, wx4[n].w);
        }
        if (t < BB-1) {
            #pragma unroll
            for (int n = 0; n < 2; n++)
                wx4[n] = *(const float4*)&g_wx[(size_t)((t+1)*NN + node0 + n)*256 + u*4];
        }
        #pragma unroll 8
        for (int j = 0; j < HH2; j++) {
            ulonglong2 wv = *(const ulonglong2*)&whh[j*256 + u*4];
            #pragma unroll
            for (int n = 0; n < 2; n++) {
                float hv = hsh[j*10 + nq*2 + n];
                ull hv2 = pack2(hv, hv);
                acc[n][0] = ffma2(wv.x, hv2, acc[n][0]);
                acc[n][1] = ffma2(wv.y, hv2, acc[n][1]);
            }
        }
        __syncthreads();
        #pragma unroll
        for (int n = 0; n < 2; n++) {
            float gi,gf,gg,go;
            unpack2(acc[n][0], gi, gf);
            unpack2(acc[n][1], gg, go);
            c[n] = fsig(gf)*c[n] + fsig(gi)*ftanh(gg);
            float h = fsig(go)*ftanh(c[n]);
            hsh[u*10 + nq*2 + n] = h;
        }
        __syncthreads();

        ull whacc = 0ull;
        #pragma unroll 8
        for (int j = 0; j < HH2; j++) {
            ull h2 = *(const ull*)&hsh[j*10 + nq*2];
            whacc = ffma2(wgd[j*64 + u], h2, whacc);
        }
        float wh0, wh1;
        unpack2(whacc, wh0, wh1);
        g_Wh[(size_t)(t*NN + node0)*HH2 + u]     = wh0;
        g_Wh[(size_t)(t*NN + node0 + 1)*HH2 + u] = wh1;

        ull sp = fmul2(whacc, as2);
        ull dp = fmul2(whacc, ad2);
        #pragma unroll
        for (int o = 16; o > 0; o >>= 1) {
            sp = fadd2(sp, __shfl_xor_sync(0xffffffffu, sp, o));
            dp = fadd2(dp, __shfl_xor_sync(0xffffffffu, dp, o));
        }
        if (lane == 0) { red_s[w] = sp; red_d[w] = dp; }
        __syncthreads();
        if (tid < 4) {
            ull st = fadd2(red_s[tid*2], red_s[tid*2 + 1]);
            ull dt = fadd2(red_d[tid*2], red_d[tid*2 + 1]);
            float s0, s1, d0, d1;
            unpack2(st, s0, s1);
            unpack2(dt, d0, d1);
            int nb = blockIdx.x*8 + tid*2;
            g_s[t*NN + nb]     = s0;
            g_s[t*NN + nb + 1] = s1;
            g_d[t*NN + nb]     = d0;
            g_d[t*NN + nb + 1] = d1;
            atomicMax(&dml[t], fkey(fmaxf(d0, d1)));
        }
    }
    __syncthreads();
    if (tid < 8) atomicMax(&g_dmaxb[tid], dml[tid]);
}

// ============================================================================
// Kernel 3: GAT on bitmask. TI=256, SPLIT=4, thread tile 8x8. unroll 4.
// ============================================================================
__global__ void __launch_bounds__(256, 2) k_gat() {
    extern __shared__ char smraw[];
    ull*   whs = (ull*)smraw;                      // [jj][c] dup pairs, 32KB
    float* PsT = (float*)(smraw + 32768);          // [jj][ii] stride PS, 66KB
    __shared__ float4 row_sh[TI];

    int tid = threadIdx.x, lane = tid & 31, w = tid >> 5;
    int b = blockIdx.y, i0 = blockIdx.x * TI, sp = blockIdx.z;

    float dmax = fdec(g_dmaxb[b]);
    {
        float s = g_s[b*NN + i0 + tid];
        float sm = s + dmax;
        float M = sm > 0.f ? sm : 0.2f*sm;
        row_sh[tid] = make_float4(-s, __expf(sm - M), __expf(0.2f*sm - M), 0.f);
    }

    int rg  = tid >> 3;
    int cgp = tid & 7;
    ull acc[4][8];
    #pragma unroll
    for (int rp = 0; rp < 4; rp++)
        #pragma unroll
        for (int k = 0; k < 8; k++) acc[rp][k] = 0ull;
    ull lacc[4] = {0ull, 0ull, 0ull, 0ull};

    const int JT = (NN/64)/SPLIT;
    const ull* mbase = g_amask + (size_t)(b*NN + i0) * NWORDS;

    for (int jtl = 0; jtl < JT; jtl++) {
        int jtg = sp * JT + jtl;
        int j0  = jtg * 64;
        __syncthreads();

        for (int i = tid; i < 2048; i += 256) {
            float2 v = *(const float2*)&g_Wh[(size_t)(b*NN + j0)*64 + 2*i];
            whs[2*i]   = pack2(v.x, v.x);
            whs[2*i+1] = pack2(v.y, v.y);
        }

        float d0 = g_d[b*NN + j0 + lane];
        float d1 = g_d[b*NN + j0 + lane + 32];
        float bp0 = __expf(d0 - dmax);
        float bp1 = __expf(d1 - dmax);
        float bm0 = __expf(0.2f*(d0 - dmax));
        float bm1 = __expf(0.2f*(d1 - dmax));

        #pragma unroll
        for (int batch = 0; batch < 4; batch++) {
            ull aw[8];
            #pragma unroll
            for (int q = 0; q < 8; q++)
                aw[q] = mbase[(size_t)(w*32 + batch*8 + q)*NWORDS + jtg];
            #pragma unroll
            for (int q = 0; q < 8; q++) {
                int ii = w*32 + batch*8 + q;
                float4 rs = row_sh[ii];
                float c0 = (d0 > rs.x) ? rs.y*bp0 : rs.z*bm0;
                float c1 = (d1 > rs.x) ? rs.y*bp1 : rs.z*bm1;
                c0 = ((unsigned)(aw[q] >> lane) & 1u)        ? c0 : 0.f;
                c1 = ((unsigned)(aw[q] >> (lane + 32)) & 1u) ? c1 : 0.f;
                PsT[lane*PS + ii]      = c0;
                PsT[(lane+32)*PS + ii] = c1;
            }
        }
        __syncthreads();

        const float* pbase = PsT + rg*8;
        const ull*   wbase = whs + cgp;
        #pragma unroll 4
        for (int jj = 0; jj < 64; jj++) {
            ull pp[4];
            #pragma unroll
            for (int rp = 0; rp < 4; rp++)
                pp[rp] = *(const ull*)&pbase[jj*PS + 2*rp];
            #pragma unroll
            for (int rp = 0; rp < 4; rp++)
                lacc[rp] = fadd2(lacc[rp], pp[rp]);
            #pragma unroll
            for (int k = 0; k < 8; k++) {
                ull wd = wbase[jj*64 + 8*k];
                #pragma unroll
                for (int rp = 0; rp < 4; rp++)
                    acc[rp][k] = ffma2(wd, pp[rp], acc[rp][k]);
            }
        }
    }

    if (cgp == 0) {
        size_t lb = (size_t)sp*ROWS_TOT + b*NN + i0 + rg*8;
        #pragma unroll
        for (int rp = 0; rp < 4; rp++) {
            float l0, l1;
            unpack2(lacc[rp], l0, l1);
            g_pl[lb + 2*rp]     = l0;
            g_pl[lb + 2*rp + 1] = l1;
        }
    }
    #pragma unroll
    for (int rp = 0; rp < 4; rp++) {
        size_t base0 = ((size_t)sp*ROWS_TOT + b*NN + i0 + rg*8 + 2*rp)     * HH2;
        size_t base1 = ((size_t)sp*ROWS_TOT + b*NN + i0 + rg*8 + 2*rp + 1) * HH2;
        #pragma unroll
        for (int k = 0; k < 8; k++) {
            float va, vb;
            unpack2(acc[rp][k], va, vb);
            g_pacc[base0 + cgp + 8*k] = va;
            g_pacc[base1 + cgp + 8*k] = vb;
        }
    }
}

// ============================================================================
// Kernel 4: combine additive split-K partials; normalize + elu.
// ============================================================================
__global__ void k_comb(float* __restrict__ out) {
    int tid = threadIdx.x;
    int r = blockIdx.x * 4 + (tid >> 6);
    int c = tid & 63;
    float l = 0.f, val = 0.f;
    #pragma unroll
    for (int s = 0; s < SPLIT; s++) {
        l   += g_pl[s*ROWS_TOT + r];
        val += g_pacc[((size_t)s*ROWS_TOT + r)*HH2 + c];
    }
    if (!(l > 0.f)) l = 1.f;
    float z = val / l;
    out[(size_t)r*HH2 + c] = z > 0.f ? z : expm1f(z);
}

// ============================================================================
extern "C" void kernel_launch(void* const* d_in, const int* in_sizes, int n_in,
                              void* d_out, int out_size) {
    const float* hist  = (const float*)d_in[0];
    const int*   adj   = (const int*)  d_in[1];
    const float* W1    = (const float*)d_in[2];
    const float* b1    = (const float*)d_in[3];
    const float* W_ih  = (const float*)d_in[4];
    const float* W_hh  = (const float*)d_in[5];
    const float* b_ih  = (const float*)d_in[6];
    const float* b_hh  = (const float*)d_in[7];
    const float* Wg    = (const float*)d_in[8];
    const float* a_src = (const float*)d_in[9];
    const float* a_dst = (const float*)d_in[10];
    float* out = (float*)d_out;

    const size_t sm_lstm = (size_t)(64*256)*4 + (size_t)(64*64)*8 + (size_t)(64*10)*4;
    const size_t sm_gat  = (size_t)32768 + (size_t)(64*PS*4);
    cudaFuncSetAttribute(k_lstm3, cudaFuncAttributeMaxDynamicSharedMemorySize, (int)sm_lstm);
    cudaFuncSetAttribute(k_gat,   cudaFuncAttributeMaxDynamicSharedMemorySize, (int)sm_gat);

    k_hw   <<<2048, 256>>>(hist, W1, b1, W_ih, b_ih, b_hh, adj);
    k_lstm3<<<256,  256, sm_lstm>>>(W_hh, Wg, a_src, a_dst);
    dim3 g4(NN/TI, BB, SPLIT);
    k_gat  <<<g4, 256, sm_gat>>>();
    k_comb <<<4096, 256>>>(out);
}